// round 16
// baseline (speedup 1.0000x reference)
#include <cuda_runtime.h>
#include <cuda_fp16.h>
#include <cstdint>

#define B_ROWS 65536
#define HDIM 1024
#define NLAYERS 8
#define FIN 26
#define EPSV 1e-5f

__device__ __half g_a0[(size_t)B_ROWS * HDIM];
__device__ __half g_a1[(size_t)B_ROWS * HDIM];
__device__ __half g_xpad16[(size_t)B_ROWS * 64];
__device__ __half g_w16[(size_t)NLAYERS * HDIM * HDIM];   // gamma ⊙ W, fp16
__device__ __half g_wstem16[HDIM * 64];
__device__ float2 g_part0[(size_t)B_ROWS * 8];
__device__ float2 g_part1[(size_t)B_ROWS * 8];
__device__ float  g_c1[NLAYERS * HDIM];
__device__ float  g_c2[NLAYERS * HDIM];

__device__ __forceinline__ uint32_t smem_u32(const void* p) {
    uint32_t a;
    asm("{ .reg .u64 t; cvta.to.shared.u64 t, %1; cvt.u32.u64 %0, t; }" : "=r"(a) : "l"(p));
    return a;
}

// ---------------- fp16 mma.sync GEMM: R11 tiling, KC=32, 3-stage pipeline ----------
// CTA tile 64x128, 128 thr, warps 2(M)x2(N), warp tile 32x64. K-chunk 32, 3 smem
// stages (15.4KB each), 4 CTAs/SM. wait_group 1: consume stage loaded 2 iters ago.
#define KC 32
#define KP 40
#define TM 64
#define STAGE_B ((TM + 128) * KP * 2)      // 15360 bytes
#define GEMM_SMEM (3 * STAGE_B)            // 46080

__global__ void __launch_bounds__(128, 4) gemm16(
    const __half* __restrict__ A, int lda,
    const __half* __restrict__ W, int ldw,
    const float2* __restrict__ part_in,
    const float* __restrict__ c1, const float* __restrict__ c2,
    __half* __restrict__ out16, float2* __restrict__ part_out,
    int nk, int fused)
{
    extern __shared__ __half smem[];
    const int tid = threadIdx.x;
    const int wid = tid >> 5, lane = tid & 31;
    const int warpM = wid & 1, warpN = wid >> 1;
    const int m0 = blockIdx.y * TM, n0 = blockIdx.x * 128;
    const uint32_t base = smem_u32(smem);

    auto load_stage = [&](int ki, int s) {
        const uint32_t st = base + (uint32_t)s * STAGE_B;
#pragma unroll
        for (int i = 0; i < 2; i++) {       // A: 64 rows x 64B
            const int seg = tid + i * 128;
            const int row = seg >> 2, c16 = seg & 3;
            const __half* src = A + (size_t)(m0 + row) * lda + ki * KC + c16 * 8;
            asm volatile("cp.async.cg.shared.global [%0], [%1], 16;"
                         :: "r"(st + row * 80 + c16 * 16), "l"(src));
        }
#pragma unroll
        for (int i = 0; i < 4; i++) {       // B: 128 rows x 64B
            const int seg = tid + i * 128;
            const int row = seg >> 2, c16 = seg & 3;
            const __half* src = W + (size_t)(n0 + row) * ldw + ki * KC + c16 * 8;
            asm volatile("cp.async.cg.shared.global [%0], [%1], 16;"
                         :: "r"(st + TM * 80 + row * 80 + c16 * 16), "l"(src));
        }
        asm volatile("cp.async.commit_group;" ::: "memory");
    };

    const int aRow = warpM * 32 + (lane & 7) + ((lane >> 3) & 1) * 8;
    const int aK   = (lane >> 4) * 8;
    const int bN   = warpN * 64 + (lane & 7) + (lane >> 4) * 8;
    const int bK   = ((lane >> 3) & 1) * 8;

    float acc[2][8][4];
#pragma unroll
    for (int mi = 0; mi < 2; mi++)
#pragma unroll
        for (int nj = 0; nj < 8; nj++)
#pragma unroll
            for (int q = 0; q < 4; q++) acc[mi][nj][q] = 0.f;

    load_stage(0, 0);
    if (nk > 1) load_stage(1, 1);

    int sidx = 0;
    for (int ki = 0; ki < nk; ki++) {
        if (ki + 1 < nk) asm volatile("cp.async.wait_group 1;" ::: "memory");
        else             asm volatile("cp.async.wait_group 0;" ::: "memory");
        __syncthreads();   // stage sidx ready; all warps done with the stage being refilled
        if (ki + 2 < nk) {
            int ns = sidx + 2;
            if (ns >= 3) ns -= 3;
            load_stage(ki + 2, ns);
        }

        const uint32_t As = base + (uint32_t)sidx * STAGE_B;
        const uint32_t Bs = As + TM * 80;
#pragma unroll
        for (int k0 = 0; k0 < KC; k0 += 16) {
            uint32_t a[2][4], b[4][4];
#pragma unroll
            for (int mi = 0; mi < 2; mi++) {
                const uint32_t ad = As + (uint32_t)((aRow + mi * 16) * KP + k0 + aK) * 2;
                asm volatile("ldmatrix.sync.aligned.m8n8.x4.shared.b16 {%0,%1,%2,%3}, [%4];"
                             : "=r"(a[mi][0]), "=r"(a[mi][1]), "=r"(a[mi][2]), "=r"(a[mi][3])
                             : "r"(ad));
            }
#pragma unroll
            for (int p = 0; p < 4; p++) {
                const uint32_t bd = Bs + (uint32_t)((bN + p * 16) * KP + k0 + bK) * 2;
                asm volatile("ldmatrix.sync.aligned.m8n8.x4.shared.b16 {%0,%1,%2,%3}, [%4];"
                             : "=r"(b[p][0]), "=r"(b[p][1]), "=r"(b[p][2]), "=r"(b[p][3])
                             : "r"(bd));
            }
#pragma unroll
            for (int mi = 0; mi < 2; mi++)
#pragma unroll
                for (int nj = 0; nj < 8; nj++) {
                    const uint32_t b0 = b[nj >> 1][(nj & 1) * 2];
                    const uint32_t b1 = b[nj >> 1][(nj & 1) * 2 + 1];
                    asm volatile(
                        "mma.sync.aligned.m16n8k16.row.col.f32.f16.f16.f32 "
                        "{%0,%1,%2,%3}, {%4,%5,%6,%7}, {%8,%9}, {%0,%1,%2,%3};"
                        : "+f"(acc[mi][nj][0]), "+f"(acc[mi][nj][1]),
                          "+f"(acc[mi][nj][2]), "+f"(acc[mi][nj][3])
                        : "r"(a[mi][0]), "r"(a[mi][1]), "r"(a[mi][2]), "r"(a[mi][3]),
                          "r"(b0), "r"(b1));
                }
        }
        if (++sidx == 3) sidx = 0;
    }

    // ---- epilogue ----
    __syncthreads();
    float* sm = (float*)smem;        // [0..127]: per-row (r, rm); [128..]: partials
    float* pm = sm + 128;
    if (fused) {
        if (tid < TM) {
            const float2* p = part_in + (size_t)(m0 + tid) * 8;
            float s = 0.f, sq = 0.f;
#pragma unroll
            for (int i = 0; i < 8; i++) { const float2 v = p[i]; s += v.x; sq += v.y; }
            const float mean = s * (1.f / HDIM);
            const float var = sq * (1.f / HDIM) - mean * mean;
            const float r = rsqrtf(var + EPSV);
            sm[tid * 2] = r;
            sm[tid * 2 + 1] = -r * mean;
        }
        __syncthreads();
    }

#pragma unroll
    for (int mi = 0; mi < 2; mi++) {
#pragma unroll
        for (int h = 0; h < 2; h++) {
            const int r_local = warpM * 32 + mi * 16 + (lane >> 2) + h * 8;
            const int grow = m0 + r_local;
            float r = 1.f, rm = 0.f;
            if (fused) { r = sm[r_local * 2]; rm = sm[r_local * 2 + 1]; }
            float s = 0.f, sq = 0.f;
#pragma unroll
            for (int nj = 0; nj < 8; nj++) {
                const int col = n0 + warpN * 64 + nj * 8 + (lane & 3) * 2;
                float c1a = 0.f, c1b = 0.f;
                if (fused) { c1a = __ldg(c1 + col); c1b = __ldg(c1 + col + 1); }
                const float c2a = __ldg(c2 + col), c2b = __ldg(c2 + col + 1);
                const float v0 = fmaxf(fmaf(r, acc[mi][nj][h * 2 + 0], fmaf(rm, c1a, c2a)), 0.f);
                const float v1 = fmaxf(fmaf(r, acc[mi][nj][h * 2 + 1], fmaf(rm, c1b, c2b)), 0.f);
                *(__half2*)(out16 + (size_t)grow * HDIM + col) = __floats2half2_rn(v0, v1);
                s += v0 + v1;
                sq += v0 * v0 + v1 * v1;
            }
            s  += __shfl_xor_sync(0xFFFFFFFFu, s, 1);
            s  += __shfl_xor_sync(0xFFFFFFFFu, s, 2);
            sq += __shfl_xor_sync(0xFFFFFFFFu, sq, 1);
            sq += __shfl_xor_sync(0xFFFFFFFFu, sq, 2);
            if ((lane & 3) == 0) {
                pm[(warpN * TM + r_local) * 2 + 0] = s;
                pm[(warpN * TM + r_local) * 2 + 1] = sq;
            }
        }
    }
    __syncthreads();
    if (tid < TM) {
        float s = 0.f, sq = 0.f;
#pragma unroll
        for (int w = 0; w < 2; w++) {
            s  += pm[(w * TM + tid) * 2 + 0];
            sq += pm[(w * TM + tid) * 2 + 1];
        }
        part_out[(size_t)(m0 + tid) * 8 + blockIdx.x] = make_float2(s, sq);
    }
}

// ---------------- merged prep: wprep / stem_wpad / stem_prep ----------------
#define WPREP_BLKS (NLAYERS * HDIM)                  // 8192
#define WPAD_BLKS  ((HDIM * 64) / 128)               // 512
#define SPREP_BLKS (B_ROWS / 4)                      // 16384
#define PREP_GRID  (WPREP_BLKS + WPAD_BLKS + SPREP_BLKS)

__global__ void __launch_bounds__(128) prep_all(
    const float* __restrict__ blk_w, const float* __restrict__ blk_gamma,
    const float* __restrict__ blk_beta, const float* __restrict__ blk_bias,
    const float* __restrict__ st_w,
    const float* __restrict__ x, const float* __restrict__ st_gamma,
    const float* __restrict__ st_beta)
{
    const int bid = blockIdx.x;
    const int tid = threadIdx.x;
    if (bid < WPREP_BLKS) {
        __shared__ float r1[4], r2[4];
        const int n = bid;
        const int l = n >> 10, nl = n & 1023;
        const float* wr = blk_w + (size_t)n * HDIM;
        const float* g = blk_gamma + l * HDIM;
        const float* bt = blk_beta + l * HDIM;
        float s1 = 0.f, s2 = 0.f;
        for (int k = tid; k < HDIM; k += 128) {
            const float wv = wr[k], gv = g[k];
            g_w16[(size_t)n * HDIM + k] = __float2half_rn(gv * wv);
            s1 += gv * wv;
            s2 += bt[k] * wv;
        }
#pragma unroll
        for (int o = 16; o > 0; o >>= 1) {
            s1 += __shfl_xor_sync(0xFFFFFFFFu, s1, o);
            s2 += __shfl_xor_sync(0xFFFFFFFFu, s2, o);
        }
        const int wi = tid >> 5;
        if ((tid & 31) == 0) { r1[wi] = s1; r2[wi] = s2; }
        __syncthreads();
        if (tid == 0) {
            g_c1[n] = r1[0] + r1[1] + r1[2] + r1[3];
            g_c2[n] = r2[0] + r2[1] + r2[2] + r2[3] + blk_bias[l * HDIM + nl];
        }
    } else if (bid < WPREP_BLKS + WPAD_BLKS) {
        const int i = (bid - WPREP_BLKS) * 128 + tid;
        const int j = i >> 6, k = i & 63;
        g_wstem16[i] = __float2half_rn((k < FIN) ? st_w[j * FIN + k] : 0.f);
    } else {
        const int warp = (bid - WPREP_BLKS - WPAD_BLKS) * 4 + (tid >> 5);
        const int lane = tid & 31;
        float v = (lane < FIN) ? x[(size_t)warp * FIN + lane] : 0.f;
        float s = v, sq = v * v;
#pragma unroll
        for (int o = 16; o > 0; o >>= 1) {
            s += __shfl_xor_sync(0xFFFFFFFFu, s, o);
            sq += __shfl_xor_sync(0xFFFFFFFFu, sq, o);
        }
        const float mean = s / (float)FIN;
        const float rstd = rsqrtf(sq / (float)FIN - mean * mean + EPSV);
        float ov = 0.f;
        if (lane < FIN) ov = (v - mean) * rstd * st_gamma[lane] + st_beta[lane];
        g_xpad16[(size_t)warp * 64 + lane] = __float2half_rn(ov);
        g_xpad16[(size_t)warp * 64 + 32 + lane] = __half(0.f);
    }
}

// ---------------- head: stats from partials, sigmoid(LN(h) @ w^T + b) ----------------
__global__ void head16(const float* __restrict__ g, const float* __restrict__ bb,
                       const float* __restrict__ w, const float* __restrict__ b1,
                       const __half* __restrict__ act, const float2* __restrict__ part,
                       float* __restrict__ out)
{
    __shared__ float red[8];
    __shared__ float2 stat;
    const int tid = threadIdx.x;
    const int row = blockIdx.x;
    if (tid == 0) {
        const float2* p = part + (size_t)row * 8;
        float s = 0.f, sq = 0.f;
#pragma unroll
        for (int i = 0; i < 8; i++) { const float2 v = p[i]; s += v.x; sq += v.y; }
        const float mean = s * (1.f / HDIM);
        const float r = rsqrtf(sq * (1.f / HDIM) - mean * mean + EPSV);
        stat = make_float2(r, -r * mean);
    }
    __syncthreads();
    const float2 st = stat;
    const __half2* hrow = (const __half2*)(act + (size_t)row * HDIM);
    const int c = tid * 4;
    const __half2 h01 = hrow[tid * 2], h23 = hrow[tid * 2 + 1];
    const float4 gg = *(const float4*)(g + c);
    const float4 bv = *(const float4*)(bb + c);
    const float4 wv = *(const float4*)(w + c);
    const float h0 = __low2float(h01), h1 = __high2float(h01);
    const float h2 = __low2float(h23), h3 = __high2float(h23);
    float d = ((h0 * st.x + st.y) * gg.x + bv.x) * wv.x +
              ((h1 * st.x + st.y) * gg.y + bv.y) * wv.y +
              ((h2 * st.x + st.y) * gg.z + bv.z) * wv.z +
              ((h3 * st.x + st.y) * gg.w + bv.w) * wv.w;
#pragma unroll
    for (int o = 16; o > 0; o >>= 1)
        d += __shfl_xor_sync(0xFFFFFFFFu, d, o);
    const int wI = tid >> 5, l = tid & 31;
    if (l == 0) red[wI] = d;
    __syncthreads();
    if (tid == 0) {
        const float a = red[0] + red[1] + red[2] + red[3] + red[4] + red[5] + red[6] + red[7];
        out[row] = 1.f / (1.f + expf(-(a + b1[0])));
    }
}

extern "C" void kernel_launch(void* const* d_in, const int* in_sizes, int n_in,
                              void* d_out, int out_size)
{
    const float* x          = (const float*)d_in[0];
    const float* st_gamma   = (const float*)d_in[1];
    const float* st_beta    = (const float*)d_in[2];
    const float* st_w       = (const float*)d_in[3];
    const float* st_b       = (const float*)d_in[4];
    const float* blk_gamma  = (const float*)d_in[5];
    const float* blk_beta   = (const float*)d_in[6];
    const float* blk_w      = (const float*)d_in[7];
    const float* blk_b      = (const float*)d_in[8];
    const float* last_gamma = (const float*)d_in[9];
    const float* last_beta  = (const float*)d_in[10];
    const float* last_w     = (const float*)d_in[11];
    const float* last_b     = (const float*)d_in[12];
    float* out = (float*)d_out;

    static bool attr_done = false;
    if (!attr_done) {
        cudaFuncSetAttribute(gemm16, cudaFuncAttributeMaxDynamicSharedMemorySize, GEMM_SMEM);
        attr_done = true;
    }

    __half* a0;    cudaGetSymbolAddress((void**)&a0, g_a0);
    __half* a1;    cudaGetSymbolAddress((void**)&a1, g_a1);
    __half* xpad;  cudaGetSymbolAddress((void**)&xpad, g_xpad16);
    __half* w16;   cudaGetSymbolAddress((void**)&w16, g_w16);
    __half* wstem; cudaGetSymbolAddress((void**)&wstem, g_wstem16);
    float2* part0; cudaGetSymbolAddress((void**)&part0, g_part0);
    float2* part1; cudaGetSymbolAddress((void**)&part1, g_part1);
    float* c1;     cudaGetSymbolAddress((void**)&c1, g_c1);
    float* c2;     cudaGetSymbolAddress((void**)&c2, g_c2);

    prep_all<<<PREP_GRID, 128>>>(blk_w, blk_gamma, blk_beta, blk_b,
                                 st_w, x, st_gamma, st_beta);

    // stem: K=64 (nk=2), plain epilogue (fused=0), writes part0
    gemm16<<<dim3(HDIM / 128, B_ROWS / TM), 128, GEMM_SMEM>>>(
        xpad, 64, wstem, 64, nullptr, nullptr, st_b, a0, part0, 2, 0);

    __half* abuf[2] = { a0, a1 };
    float2* pbuf[2] = { part0, part1 };
    for (int l = 0; l < NLAYERS; l++) {
        gemm16<<<dim3(HDIM / 128, B_ROWS / TM), 128, GEMM_SMEM>>>(
            abuf[l & 1], HDIM, w16 + (size_t)l * HDIM * HDIM, HDIM,
            pbuf[l & 1], c1 + l * HDIM, c2 + l * HDIM,
            abuf[(l & 1) ^ 1], pbuf[(l & 1) ^ 1], HDIM / KC, 1);
    }

    head16<<<B_ROWS, 256>>>(last_gamma, last_beta, last_w, last_b, a0, part0, out);
}

// round 17
// speedup vs baseline: 1.1931x; 1.1931x over previous
#include <cuda_runtime.h>
#include <cuda_fp16.h>
#include <cstdint>

#define B_ROWS 65536
#define HDIM 1024
#define NLAYERS 8
#define FIN 26
#define EPSV 1e-5f

__device__ __half g_a0[(size_t)B_ROWS * HDIM];
__device__ __half g_a1[(size_t)B_ROWS * HDIM];
__device__ __half g_xpad16[(size_t)B_ROWS * 64];
__device__ __half g_w16[(size_t)NLAYERS * HDIM * HDIM];   // gamma ⊙ W, fp16
__device__ __half g_wstem16[HDIM * 64];
__device__ float2 g_part0[(size_t)B_ROWS * 8];
__device__ float2 g_part1[(size_t)B_ROWS * 8];
__device__ float  g_c1[NLAYERS * HDIM];
__device__ float  g_c2[NLAYERS * HDIM];

__device__ __forceinline__ uint32_t smem_u32(const void* p) {
    uint32_t a;
    asm("{ .reg .u64 t; cvta.to.shared.u64 t, %1; cvt.u32.u64 %0, t; }" : "=r"(a) : "l"(p));
    return a;
}

// ---------------- fp16 mma.sync GEMM (R14 config — best measured, 3576us) ----------
// CTA tile 64x128, 128 thr, warps 2(M)x2(N), warp tile 32x64. K-chunk 64, 2 stages,
// 4 CTAs/SM. Double-buffer: wait_group 0 -> barrier -> issue next load.
#define KC 64
#define KP 72
#define TM 64
#define STAGE_B ((TM + 128) * KP * 2)      // 27648 bytes
#define GEMM_SMEM (2 * STAGE_B)            // 55296

__global__ void __launch_bounds__(128, 4) gemm16(
    const __half* __restrict__ A, int lda,
    const __half* __restrict__ W, int ldw,
    const float2* __restrict__ part_in,
    const float* __restrict__ c1, const float* __restrict__ c2,
    __half* __restrict__ out16, float2* __restrict__ part_out,
    int nk, int fused)
{
    extern __shared__ __half smem[];
    const int tid = threadIdx.x;
    const int wid = tid >> 5, lane = tid & 31;
    const int warpM = wid & 1, warpN = wid >> 1;
    const int m0 = blockIdx.y * TM, n0 = blockIdx.x * 128;
    const uint32_t base = smem_u32(smem);

    auto load_stage = [&](int ki, int s) {
        const uint32_t st = base + (uint32_t)s * STAGE_B;
#pragma unroll
        for (int i = 0; i < 4; i++) {       // A: 64 rows x 128B
            const int seg = tid + i * 128;
            const int row = seg >> 3, c = seg & 7;
            const __half* src = A + (size_t)(m0 + row) * lda + ki * KC + c * 8;
            asm volatile("cp.async.cg.shared.global [%0], [%1], 16;"
                         :: "r"(st + row * 144 + c * 16), "l"(src));
        }
#pragma unroll
        for (int i = 0; i < 8; i++) {       // B: 128 rows x 128B
            const int seg = tid + i * 128;
            const int row = seg >> 3, c = seg & 7;
            const __half* src = W + (size_t)(n0 + row) * ldw + ki * KC + c * 8;
            asm volatile("cp.async.cg.shared.global [%0], [%1], 16;"
                         :: "r"(st + TM * 144 + row * 144 + c * 16), "l"(src));
        }
        asm volatile("cp.async.commit_group;" ::: "memory");
    };

    const int aRow = warpM * 32 + (lane & 7) + ((lane >> 3) & 1) * 8;
    const int aK   = (lane >> 4) * 8;
    const int bN   = warpN * 64 + (lane & 7) + (lane >> 4) * 8;
    const int bK   = ((lane >> 3) & 1) * 8;

    float acc[2][8][4];
#pragma unroll
    for (int mi = 0; mi < 2; mi++)
#pragma unroll
        for (int nj = 0; nj < 8; nj++)
#pragma unroll
            for (int q = 0; q < 4; q++) acc[mi][nj][q] = 0.f;

    load_stage(0, 0);

    for (int ki = 0; ki < nk; ki++) {
        const int s = ki & 1;
        asm volatile("cp.async.wait_group 0;" ::: "memory");  // stage s loaded
        __syncthreads();   // all warps done with stage s^1
        if (ki + 1 < nk) load_stage(ki + 1, s ^ 1);           // overlaps mma

        const uint32_t As = base + (uint32_t)s * STAGE_B;
        const uint32_t Bs = As + TM * 144;
#pragma unroll
        for (int k0 = 0; k0 < KC; k0 += 16) {
            uint32_t a[2][4], b[4][4];
#pragma unroll
            for (int mi = 0; mi < 2; mi++) {
                const uint32_t ad = As + (uint32_t)((aRow + mi * 16) * KP + k0 + aK) * 2;
                asm volatile("ldmatrix.sync.aligned.m8n8.x4.shared.b16 {%0,%1,%2,%3}, [%4];"
                             : "=r"(a[mi][0]), "=r"(a[mi][1]), "=r"(a[mi][2]), "=r"(a[mi][3])
                             : "r"(ad));
            }
#pragma unroll
            for (int p = 0; p < 4; p++) {
                const uint32_t bd = Bs + (uint32_t)((bN + p * 16) * KP + k0 + bK) * 2;
                asm volatile("ldmatrix.sync.aligned.m8n8.x4.shared.b16 {%0,%1,%2,%3}, [%4];"
                             : "=r"(b[p][0]), "=r"(b[p][1]), "=r"(b[p][2]), "=r"(b[p][3])
                             : "r"(bd));
            }
#pragma unroll
            for (int mi = 0; mi < 2; mi++)
#pragma unroll
                for (int nj = 0; nj < 8; nj++) {
                    const uint32_t b0 = b[nj >> 1][(nj & 1) * 2];
                    const uint32_t b1 = b[nj >> 1][(nj & 1) * 2 + 1];
                    asm volatile(
                        "mma.sync.aligned.m16n8k16.row.col.f32.f16.f16.f32 "
                        "{%0,%1,%2,%3}, {%4,%5,%6,%7}, {%8,%9}, {%0,%1,%2,%3};"
                        : "+f"(acc[mi][nj][0]), "+f"(acc[mi][nj][1]),
                          "+f"(acc[mi][nj][2]), "+f"(acc[mi][nj][3])
                        : "r"(a[mi][0]), "r"(a[mi][1]), "r"(a[mi][2]), "r"(a[mi][3]),
                          "r"(b0), "r"(b1));
                }
        }
    }

    // ---- epilogue ----
    __syncthreads();
    float* sm = (float*)smem;        // [0..127]: per-row (r, rm); [128..]: partials
    float* pm = sm + 128;
    if (fused) {
        if (tid < TM) {
            const float2* p = part_in + (size_t)(m0 + tid) * 8;
            float s = 0.f, sq = 0.f;
#pragma unroll
            for (int i = 0; i < 8; i++) { const float2 v = p[i]; s += v.x; sq += v.y; }
            const float mean = s * (1.f / HDIM);
            const float var = sq * (1.f / HDIM) - mean * mean;
            const float r = rsqrtf(var + EPSV);
            sm[tid * 2] = r;
            sm[tid * 2 + 1] = -r * mean;
        }
        __syncthreads();
    }

#pragma unroll
    for (int mi = 0; mi < 2; mi++) {
#pragma unroll
        for (int h = 0; h < 2; h++) {
            const int r_local = warpM * 32 + mi * 16 + (lane >> 2) + h * 8;
            const int grow = m0 + r_local;
            float r = 1.f, rm = 0.f;
            if (fused) { r = sm[r_local * 2]; rm = sm[r_local * 2 + 1]; }
            float s = 0.f, sq = 0.f;
#pragma unroll
            for (int nj = 0; nj < 8; nj++) {
                const int col = n0 + warpN * 64 + nj * 8 + (lane & 3) * 2;
                float2 c1v = make_float2(0.f, 0.f);
                if (fused) c1v = __ldg((const float2*)(c1 + col));
                const float2 c2v = __ldg((const float2*)(c2 + col));
                const float v0 = fmaxf(fmaf(r, acc[mi][nj][h * 2 + 0], fmaf(rm, c1v.x, c2v.x)), 0.f);
                const float v1 = fmaxf(fmaf(r, acc[mi][nj][h * 2 + 1], fmaf(rm, c1v.y, c2v.y)), 0.f);
                *(__half2*)(out16 + (size_t)grow * HDIM + col) = __floats2half2_rn(v0, v1);
                s += v0 + v1;
                sq += v0 * v0 + v1 * v1;
            }
            s  += __shfl_xor_sync(0xFFFFFFFFu, s, 1);
            s  += __shfl_xor_sync(0xFFFFFFFFu, s, 2);
            sq += __shfl_xor_sync(0xFFFFFFFFu, sq, 1);
            sq += __shfl_xor_sync(0xFFFFFFFFu, sq, 2);
            if ((lane & 3) == 0) {
                pm[(warpN * TM + r_local) * 2 + 0] = s;
                pm[(warpN * TM + r_local) * 2 + 1] = sq;
            }
        }
    }
    __syncthreads();
    if (tid < TM) {
        float s = 0.f, sq = 0.f;
#pragma unroll
        for (int w = 0; w < 2; w++) {
            s  += pm[(w * TM + tid) * 2 + 0];
            sq += pm[(w * TM + tid) * 2 + 1];
        }
        part_out[(size_t)(m0 + tid) * 8 + blockIdx.x] = make_float2(s, sq);
    }
}

// ---------------- merged prep: wprep / stem_wpad / stem_prep ----------------
#define WPREP_BLKS (NLAYERS * HDIM)                  // 8192
#define WPAD_BLKS  ((HDIM * 64) / 128)               // 512
#define SPREP_BLKS (B_ROWS / 4)                      // 16384
#define PREP_GRID  (WPREP_BLKS + WPAD_BLKS + SPREP_BLKS)

__global__ void __launch_bounds__(128) prep_all(
    const float* __restrict__ blk_w, const float* __restrict__ blk_gamma,
    const float* __restrict__ blk_beta, const float* __restrict__ blk_bias,
    const float* __restrict__ st_w,
    const float* __restrict__ x, const float* __restrict__ st_gamma,
    const float* __restrict__ st_beta)
{
    const int bid = blockIdx.x;
    const int tid = threadIdx.x;
    if (bid < WPREP_BLKS) {
        __shared__ float r1[4], r2[4];
        const int n = bid;
        const int l = n >> 10, nl = n & 1023;
        const float* wr = blk_w + (size_t)n * HDIM;
        const float* g = blk_gamma + l * HDIM;
        const float* bt = blk_beta + l * HDIM;
        float s1 = 0.f, s2 = 0.f;
        for (int k = tid; k < HDIM; k += 128) {
            const float wv = wr[k], gv = g[k];
            g_w16[(size_t)n * HDIM + k] = __float2half_rn(gv * wv);
            s1 += gv * wv;
            s2 += bt[k] * wv;
        }
#pragma unroll
        for (int o = 16; o > 0; o >>= 1) {
            s1 += __shfl_xor_sync(0xFFFFFFFFu, s1, o);
            s2 += __shfl_xor_sync(0xFFFFFFFFu, s2, o);
        }
        const int wi = tid >> 5;
        if ((tid & 31) == 0) { r1[wi] = s1; r2[wi] = s2; }
        __syncthreads();
        if (tid == 0) {
            g_c1[n] = r1[0] + r1[1] + r1[2] + r1[3];
            g_c2[n] = r2[0] + r2[1] + r2[2] + r2[3] + blk_bias[l * HDIM + nl];
        }
    } else if (bid < WPREP_BLKS + WPAD_BLKS) {
        const int i = (bid - WPREP_BLKS) * 128 + tid;
        const int j = i >> 6, k = i & 63;
        g_wstem16[i] = __float2half_rn((k < FIN) ? st_w[j * FIN + k] : 0.f);
    } else {
        const int warp = (bid - WPREP_BLKS - WPAD_BLKS) * 4 + (tid >> 5);
        const int lane = tid & 31;
        float v = (lane < FIN) ? x[(size_t)warp * FIN + lane] : 0.f;
        float s = v, sq = v * v;
#pragma unroll
        for (int o = 16; o > 0; o >>= 1) {
            s += __shfl_xor_sync(0xFFFFFFFFu, s, o);
            sq += __shfl_xor_sync(0xFFFFFFFFu, sq, o);
        }
        const float mean = s / (float)FIN;
        const float rstd = rsqrtf(sq / (float)FIN - mean * mean + EPSV);
        float ov = 0.f;
        if (lane < FIN) ov = (v - mean) * rstd * st_gamma[lane] + st_beta[lane];
        g_xpad16[(size_t)warp * 64 + lane] = __float2half_rn(ov);
        g_xpad16[(size_t)warp * 64 + 32 + lane] = __half(0.f);
    }
}

// ---------------- head: warp-per-row; stats from partials; sigmoid(LN(h)@w^T+b) -----
__global__ void __launch_bounds__(256) head16(
    const float* __restrict__ g, const float* __restrict__ bb,
    const float* __restrict__ w, const float* __restrict__ b1,
    const __half* __restrict__ act, const float2* __restrict__ part,
    float* __restrict__ out)
{
    const int lane = threadIdx.x & 31;
    const int row = blockIdx.x * 8 + (threadIdx.x >> 5);

    // stats: lanes 0..7 hold one partial each, tree-reduce over 8 lanes
    float ps = 0.f, pq = 0.f;
    if (lane < 8) {
        const float2 v = __ldg(&part[(size_t)row * 8 + lane]);
        ps = v.x; pq = v.y;
    }
#pragma unroll
    for (int o = 4; o > 0; o >>= 1) {
        ps += __shfl_xor_sync(0xFFFFFFFFu, ps, o);
        pq += __shfl_xor_sync(0xFFFFFFFFu, pq, o);
    }
    ps = __shfl_sync(0xFFFFFFFFu, ps, 0);
    pq = __shfl_sync(0xFFFFFFFFu, pq, 0);
    const float mean = ps * (1.f / HDIM);
    const float r = rsqrtf(pq * (1.f / HDIM) - mean * mean + EPSV);
    const float rm = -r * mean;

    // each lane processes 32 elements: 8 half2x2 chunks strided by warp
    const __half2* hrow = (const __half2*)(act + (size_t)row * HDIM);
    float d = 0.f;
#pragma unroll
    for (int i = 0; i < 8; i++) {
        const int e2 = lane * 2 + i * 64;           // half2 index (two consecutive)
        const __half2 hA = hrow[e2], hB = hrow[e2 + 1];
        const int c = e2 * 2;
        const float4 gg = *(const float4*)(g + c);
        const float4 bv = *(const float4*)(bb + c);
        const float4 wv = *(const float4*)(w + c);
        d += ((__low2float(hA)  * r + rm) * gg.x + bv.x) * wv.x
           + ((__high2float(hA) * r + rm) * gg.y + bv.y) * wv.y
           + ((__low2float(hB)  * r + rm) * gg.z + bv.z) * wv.z
           + ((__high2float(hB) * r + rm) * gg.w + bv.w) * wv.w;
    }
#pragma unroll
    for (int o = 16; o > 0; o >>= 1)
        d += __shfl_xor_sync(0xFFFFFFFFu, d, o);
    if (lane == 0)
        out[row] = 1.f / (1.f + expf(-(d + b1[0])));
}

extern "C" void kernel_launch(void* const* d_in, const int* in_sizes, int n_in,
                              void* d_out, int out_size)
{
    const float* x          = (const float*)d_in[0];
    const float* st_gamma   = (const float*)d_in[1];
    const float* st_beta    = (const float*)d_in[2];
    const float* st_w       = (const float*)d_in[3];
    const float* st_b       = (const float*)d_in[4];
    const float* blk_gamma  = (const float*)d_in[5];
    const float* blk_beta   = (const float*)d_in[6];
    const float* blk_w      = (const float*)d_in[7];
    const float* blk_b      = (const float*)d_in[8];
    const float* last_gamma = (const float*)d_in[9];
    const float* last_beta  = (const float*)d_in[10];
    const float* last_w     = (const float*)d_in[11];
    const float* last_b     = (const float*)d_in[12];
    float* out = (float*)d_out;

    static bool attr_done = false;
    if (!attr_done) {
        cudaFuncSetAttribute(gemm16, cudaFuncAttributeMaxDynamicSharedMemorySize, GEMM_SMEM);
        attr_done = true;
    }

    __half* a0;    cudaGetSymbolAddress((void**)&a0, g_a0);
    __half* a1;    cudaGetSymbolAddress((void**)&a1, g_a1);
    __half* xpad;  cudaGetSymbolAddress((void**)&xpad, g_xpad16);
    __half* w16;   cudaGetSymbolAddress((void**)&w16, g_w16);
    __half* wstem; cudaGetSymbolAddress((void**)&wstem, g_wstem16);
    float2* part0; cudaGetSymbolAddress((void**)&part0, g_part0);
    float2* part1; cudaGetSymbolAddress((void**)&part1, g_part1);
    float* c1;     cudaGetSymbolAddress((void**)&c1, g_c1);
    float* c2;     cudaGetSymbolAddress((void**)&c2, g_c2);

    prep_all<<<PREP_GRID, 128>>>(blk_w, blk_gamma, blk_beta, blk_b,
                                 st_w, x, st_gamma, st_beta);

    // stem: K=64 (1 chunk), plain epilogue (fused=0), writes part0
    gemm16<<<dim3(HDIM / 128, B_ROWS / TM), 128, GEMM_SMEM>>>(
        xpad, 64, wstem, 64, nullptr, nullptr, st_b, a0, part0, 1, 0);

    __half* abuf[2] = { a0, a1 };
    float2* pbuf[2] = { part0, part1 };
    for (int l = 0; l < NLAYERS; l++) {
        gemm16<<<dim3(HDIM / 128, B_ROWS / TM), 128, GEMM_SMEM>>>(
            abuf[l & 1], HDIM, w16 + (size_t)l * HDIM * HDIM, HDIM,
            pbuf[l & 1], c1 + l * HDIM, c2 + l * HDIM,
            abuf[(l & 1) ^ 1], pbuf[(l & 1) ^ 1], HDIM / KC, 1);
    }

    head16<<<B_ROWS / 8, 256>>>(last_gamma, last_beta, last_w, last_b, a0, part0, out);
}